// round 3
// baseline (speedup 1.0000x reference)
#include <cuda_runtime.h>
#include <math.h>

// ---------------------------------------------------------------------------
// NUFFT type-2:  image(8,256,256) -> kdata(2,8,131072)
//   1) de-apodization inlined in pass1
//   2) centered zero-pad 512x512 fft2 == FFT512(zero-pad) * i^{k1} * i^{k2}
//   3) KB 6x6 gather: points binned into 64x64 tiles, gather from smem tile
// ---------------------------------------------------------------------------

#define IMN   256
#define G     512
#define B_    8
#define M_    131072            // 2^17
#define J_    6
#define NBIN  512               // 8 batches * 8 * 8 tiles
#define TILE  64
#define TROWS 69                // TILE + 5 halo
#define TPITCH 71               // padded pitch (float2 units)

// Scratch (device globals: allocation-free per harness rules)
__device__ float2 g_F2T[B_ * G * IMN];               // pass1 out [b][k2][n1]
__device__ __align__(16) float2 g_KGT[B_ * G * G];   // k-grid    [b][k2][k1]
__device__ float4 g_sorted[B_ * M_];                 // (tm1,tm2,dcf,idx) binned
__device__ int    g_cnt[NBIN];
__device__ int    g_off[NBIN];
__device__ int    g_cursor[NBIN];

__device__ __forceinline__ float beta_f() {
    return (float)(3.141592653589793 * sqrt(19.45));  // Beatty beta, OS=2, J=6
}

__device__ __forceinline__ float apod1(int n) {
    float x   = (float)n - 128.0f;
    float arg = (float)(3.141592653589793) * 6.0f * x / 512.0f;
    float bb  = beta_f();
    float t   = bb * bb - arg * arg;
    float st  = sqrtf(t);
    return st / sinhf(st);
}

// Abramowitz & Stegun I0 (rel err ~2e-7)
__device__ __forceinline__ float bessi0f(float z) {
    if (z < 3.75f) {
        float t = z * z * (1.0f / 14.0625f);
        return 1.0f + t * (3.5156229f + t * (3.0899424f + t * (1.2067492f +
                     t * (0.2659732f + t * (0.0360768f + t * 0.0045813f)))));
    } else {
        float w = 3.75f / z;
        float p = 0.39894228f + w * (0.01328592f + w * (0.00225319f + w * (-0.00157565f +
                  w * (0.00916281f + w * (-0.02057706f + w * (0.02635537f +
                  w * (-0.01647633f + w * 0.00392377f)))))));
        return p * __expf(z) * rsqrtf(z);
    }
}

__device__ __forceinline__ float kb(float u) {
    float x = u * (1.0f / 3.0f);
    float t = 1.0f - x * x;
    if (t <= 0.0f) return 0.0f;
    return bessi0f(beta_f() * sqrtf(t));
}

__device__ __forceinline__ float2 mul_ik(float2 v, int k) {
    switch (k & 3) {
        case 0:  return v;
        case 1:  return make_float2(-v.y,  v.x);
        case 2:  return make_float2(-v.x, -v.y);
        default: return make_float2( v.y, -v.x);
    }
}

// In-place 512-pt radix-2 DIT FFT (input pre-bit-reversed), 128 threads.
__device__ __forceinline__ void fft512(float2* sh, int tid) {
    #pragma unroll
    for (int half = 1; half <= 256; half <<= 1) {
        float step = -3.14159265358979f / (float)half;
        __syncthreads();
        #pragma unroll
        for (int t = tid; t < 256; t += 128) {
            int pos = t & (half - 1);
            int i0  = ((t & ~(half - 1)) << 1) | pos;
            int i1  = i0 + half;
            float s, c;
            __sincosf(step * (float)pos, &s, &c);
            float2 a = sh[i0];
            float2 b = sh[i1];
            float tr = c * b.x - s * b.y;
            float ti = c * b.y + s * b.x;
            sh[i0] = make_float2(a.x + tr, a.y + ti);
            sh[i1] = make_float2(a.x - tr, a.y - ti);
        }
    }
    __syncthreads();
}

// ---------------------------------------------------------------------------
__global__ void pass1_kernel(const float* __restrict__ img) {
    int b  = blockIdx.x >> 8;
    int n1 = blockIdx.x & 255;
    int tid = threadIdx.x;
    __shared__ float2 sh[512];

    float a1 = apod1(n1);
    const float* row = img + ((size_t)b * IMN + n1) * IMN;
    #pragma unroll
    for (int n = tid; n < 512; n += 128) {
        float v = 0.0f;
        if (n < 256) v = row[n] * apod1(n) * a1;
        int br = __brev((unsigned)n) >> 23;
        sh[br] = make_float2(v, 0.0f);
    }
    fft512(sh, tid);
    #pragma unroll
    for (int k = tid; k < 512; k += 128) {
        g_F2T[((size_t)b * G + k) * IMN + n1] = mul_ik(sh[k], k);
    }
}

__global__ void pass2_kernel() {
    int b  = blockIdx.x >> 9;
    int k2 = blockIdx.x & 511;
    int tid = threadIdx.x;
    __shared__ float2 sh[512];

    const float2* src = g_F2T + ((size_t)b * G + k2) * IMN;
    #pragma unroll
    for (int n = tid; n < 512; n += 128) {
        float2 v = (n < 256) ? src[n] : make_float2(0.0f, 0.0f);
        int br = __brev((unsigned)n) >> 23;
        sh[br] = v;
    }
    fft512(sh, tid);
    float2* dst = g_KGT + ((size_t)b * G + k2) * G;
    #pragma unroll
    for (int k = tid; k < 512; k += 128) {
        dst[k] = mul_ik(sh[k], k);
    }
}

// ---------------------------------------------------------------------------
// Binning pipeline
__global__ void zero_bins_kernel() {
    g_cnt[threadIdx.x] = 0;
}

__device__ __forceinline__ int point_bin(int b, float tm1, float tm2) {
    int w1 = ((int)floorf(tm1)) & 511;   // col dim (k1)
    int w2 = ((int)floorf(tm2)) & 511;   // row dim (k2)
    return (b << 6) | ((w2 >> 6) << 3) | (w1 >> 6);
}

__global__ void count_kernel(const float* __restrict__ ktraj) {
    int idx = blockIdx.x * blockDim.x + threadIdx.x;
    int b = idx >> 17;
    int m = idx & (M_ - 1);
    const float SC = (float)(512.0 / (2.0 * 3.141592653589793));
    float tm1 = ktraj[((size_t)b * 2)     * M_ + m] * SC;
    float tm2 = ktraj[((size_t)b * 2 + 1) * M_ + m] * SC;
    atomicAdd(&g_cnt[point_bin(b, tm1, tm2)], 1);
}

__global__ void scan_kernel() {
    __shared__ int sh[NBIN];
    int tid = threadIdx.x;            // 512 threads
    int v = g_cnt[tid];
    sh[tid] = v;
    #pragma unroll
    for (int d = 1; d < NBIN; d <<= 1) {
        __syncthreads();
        int add = (tid >= d) ? sh[tid - d] : 0;
        __syncthreads();
        sh[tid] += add;
    }
    int excl = sh[tid] - v;
    g_off[tid]    = excl;
    g_cursor[tid] = excl;
}

__global__ void scatter_kernel(const float* __restrict__ ktraj,
                               const float* __restrict__ dcf) {
    int idx = blockIdx.x * blockDim.x + threadIdx.x;
    int b = idx >> 17;
    int m = idx & (M_ - 1);
    const float SC = (float)(512.0 / (2.0 * 3.141592653589793));
    float tm1 = ktraj[((size_t)b * 2)     * M_ + m] * SC;
    float tm2 = ktraj[((size_t)b * 2 + 1) * M_ + m] * SC;
    float d   = dcf[(size_t)b * M_ + m];
    int bin = point_bin(b, tm1, tm2);
    int pos = atomicAdd(&g_cursor[bin], 1);
    g_sorted[pos] = make_float4(tm1, tm2, d, __int_as_float(idx));
}

// ---------------------------------------------------------------------------
// Gather: one block per bin. Load (64+5)^2 halo tile into smem, then each
// point reads its 6x6 taps from smem.
__global__ void __launch_bounds__(256) gather_bin_kernel(float* __restrict__ out) {
    __shared__ float2 tile[TROWS * TPITCH];   // 69*71*8 = 39.2 KB

    int bin = blockIdx.x;
    int b   = bin >> 6;
    int t2  = (bin >> 3) & 7;   // row tile (k2)
    int t1  = bin & 7;          // col tile (k1)
    int tid = threadIdx.x;

    int r0 = t2 * TILE - 2;     // may be negative; wrap on use
    int c0 = t1 * TILE - 2;

    const float2* base = g_KGT + (size_t)b * G * G;
    for (int i = tid; i < TROWS * TROWS; i += 256) {
        int lr = i / TROWS;
        int lc = i - lr * TROWS;
        int gr = (r0 + lr) & 511;
        int gc = (c0 + lc) & 511;
        tile[lr * TPITCH + lc] = base[(size_t)gr * G + gc];
    }
    __syncthreads();

    int beg = g_off[bin];
    int end = beg + g_cnt[bin];

    for (int p = beg + tid; p < end; p += 256) {
        float4 pt = g_sorted[p];
        float tm1 = pt.x, tm2 = pt.y, d = pt.z;
        int idx = __float_as_int(pt.w);

        float f1 = floorf(tm1), f2 = floorf(tm2);
        float fr1 = tm1 - f1,   fr2 = tm2 - f2;
        int w1 = ((int)f1) & 511;
        int w2 = ((int)f2) & 511;
        int lc = (w1 & 63) + 2;    // 2..65
        int lr = (w2 & 63) + 2;

        float a1[J_], a2[J_];
        #pragma unroll
        for (int j = 0; j < J_; j++) {
            a1[j] = kb(fr1 - (float)(j - 2));
            a2[j] = kb(fr2 - (float)(j - 2));
        }

        float sre = 0.0f, sim = 0.0f;
        const float2* tp = tile + (lr - 2) * TPITCH + (lc - 2);
        #pragma unroll
        for (int j2 = 0; j2 < J_; j2++) {
            const float2* row = tp + j2 * TPITCH;
            float rre = 0.0f, rim = 0.0f;
            #pragma unroll
            for (int j1 = 0; j1 < J_; j1++) {
                float2 v = row[j1];
                rre = fmaf(a1[j1], v.x, rre);
                rim = fmaf(a1[j1], v.y, rim);
            }
            sre = fmaf(a2[j2], rre, sre);
            sim = fmaf(a2[j2], rim, sim);
        }

        out[idx]           = sre * d;    // (0, b, m)
        out[B_ * M_ + idx] = sim * d;    // (1, b, m)
    }
}

// ---------------------------------------------------------------------------
extern "C" void kernel_launch(void* const* d_in, const int* in_sizes, int n_in,
                              void* d_out, int out_size) {
    const float* image = (const float*)d_in[0];   // (8,256,256)
    const float* ktraj = (const float*)d_in[1];   // (8,2,131072)
    const float* dcf   = (const float*)d_in[2];   // (8,131072)
    float* out = (float*)d_out;                   // (2,8,131072)

    pass1_kernel   <<<B_ * IMN, 128>>>(image);
    pass2_kernel   <<<B_ * G,   128>>>();
    zero_bins_kernel<<<1, NBIN>>>();
    count_kernel   <<<(B_ * M_) / 256, 256>>>(ktraj);
    scan_kernel    <<<1, NBIN>>>();
    scatter_kernel <<<(B_ * M_) / 256, 256>>>(ktraj, dcf);
    gather_bin_kernel<<<NBIN, 256>>>(out);
}

// round 4
// speedup vs baseline: 3.4997x; 3.4997x over previous
#include <cuda_runtime.h>
#include <math.h>

// ---------------------------------------------------------------------------
// NUFFT type-2:  image(8,256,256) -> kdata(2,8,131072)
//   1) de-apodization inlined in pass1
//   2) centered zero-pad 512x512 fft2 == FFT512(zero-pad) * i^{k1} * i^{k2}
//   3) KB 6x6 gather: points binned into 64x64 tiles (privatized histogram),
//      gather from smem tile
// ---------------------------------------------------------------------------

#define IMN   256
#define G     512
#define B_    8
#define M_    131072            // 2^17
#define NPTS  (B_ * M_)         // 1,048,576
#define J_    6
#define NBIN  512               // 8 batches * 8 * 8 tiles
#define TILE  64
#define TROWS 69                // TILE + 5 halo
#define TPITCH 71               // padded pitch (float2 units)

#define HB    128               // histogram blocks
#define HT    512               // histogram threads/block
#define PPB   (NPTS / HB)       // 8192 points per block

// Scratch (device globals: allocation-free per harness rules)
__device__ float2 g_F2T[B_ * G * IMN];               // pass1 out [b][k2][n1]
__device__ __align__(16) float2 g_KGT[B_ * G * G];   // k-grid    [b][k2][k1]
__device__ float4 g_sorted[NPTS];                    // (tm1,tm2,dcf,idx) binned
__device__ int    g_cnt[NBIN];
__device__ int    g_off[NBIN];
__device__ int    g_cursor[NBIN];

__device__ __forceinline__ float beta_f() {
    return (float)(3.141592653589793 * sqrt(19.45));  // Beatty beta, OS=2, J=6
}

__device__ __forceinline__ float apod1(int n) {
    float x   = (float)n - 128.0f;
    float arg = (float)(3.141592653589793) * 6.0f * x / 512.0f;
    float bb  = beta_f();
    float t   = bb * bb - arg * arg;
    float st  = sqrtf(t);
    return st / sinhf(st);
}

// Abramowitz & Stegun I0 (rel err ~2e-7)
__device__ __forceinline__ float bessi0f(float z) {
    if (z < 3.75f) {
        float t = z * z * (1.0f / 14.0625f);
        return 1.0f + t * (3.5156229f + t * (3.0899424f + t * (1.2067492f +
                     t * (0.2659732f + t * (0.0360768f + t * 0.0045813f)))));
    } else {
        float w = 3.75f / z;
        float p = 0.39894228f + w * (0.01328592f + w * (0.00225319f + w * (-0.00157565f +
                  w * (0.00916281f + w * (-0.02057706f + w * (0.02635537f +
                  w * (-0.01647633f + w * 0.00392377f)))))));
        return p * __expf(z) * rsqrtf(z);
    }
}

__device__ __forceinline__ float kb(float u) {
    float x = u * (1.0f / 3.0f);
    float t = 1.0f - x * x;
    if (t <= 0.0f) return 0.0f;
    return bessi0f(beta_f() * sqrtf(t));
}

__device__ __forceinline__ float2 mul_ik(float2 v, int k) {
    switch (k & 3) {
        case 0:  return v;
        case 1:  return make_float2(-v.y,  v.x);
        case 2:  return make_float2(-v.x, -v.y);
        default: return make_float2( v.y, -v.x);
    }
}

// In-place 512-pt radix-2 DIT FFT (input pre-bit-reversed), 128 threads.
__device__ __forceinline__ void fft512(float2* sh, int tid) {
    #pragma unroll
    for (int half = 1; half <= 256; half <<= 1) {
        float step = -3.14159265358979f / (float)half;
        __syncthreads();
        #pragma unroll
        for (int t = tid; t < 256; t += 128) {
            int pos = t & (half - 1);
            int i0  = ((t & ~(half - 1)) << 1) | pos;
            int i1  = i0 + half;
            float s, c;
            __sincosf(step * (float)pos, &s, &c);
            float2 a = sh[i0];
            float2 b = sh[i1];
            float tr = c * b.x - s * b.y;
            float ti = c * b.y + s * b.x;
            sh[i0] = make_float2(a.x + tr, a.y + ti);
            sh[i1] = make_float2(a.x - tr, a.y - ti);
        }
    }
    __syncthreads();
}

// ---------------------------------------------------------------------------
__global__ void pass1_kernel(const float* __restrict__ img) {
    int b  = blockIdx.x >> 8;
    int n1 = blockIdx.x & 255;
    int tid = threadIdx.x;
    __shared__ float2 sh[512];

    float a1 = apod1(n1);
    const float* row = img + ((size_t)b * IMN + n1) * IMN;
    #pragma unroll
    for (int n = tid; n < 512; n += 128) {
        float v = 0.0f;
        if (n < 256) v = row[n] * apod1(n) * a1;
        int br = __brev((unsigned)n) >> 23;
        sh[br] = make_float2(v, 0.0f);
    }
    fft512(sh, tid);
    #pragma unroll
    for (int k = tid; k < 512; k += 128) {
        g_F2T[((size_t)b * G + k) * IMN + n1] = mul_ik(sh[k], k);
    }
}

__global__ void pass2_kernel() {
    int b  = blockIdx.x >> 9;
    int k2 = blockIdx.x & 511;
    int tid = threadIdx.x;
    __shared__ float2 sh[512];

    const float2* src = g_F2T + ((size_t)b * G + k2) * IMN;
    #pragma unroll
    for (int n = tid; n < 512; n += 128) {
        float2 v = (n < 256) ? src[n] : make_float2(0.0f, 0.0f);
        int br = __brev((unsigned)n) >> 23;
        sh[br] = v;
    }
    fft512(sh, tid);
    float2* dst = g_KGT + ((size_t)b * G + k2) * G;
    #pragma unroll
    for (int k = tid; k < 512; k += 128) {
        dst[k] = mul_ik(sh[k], k);
    }
}

// ---------------------------------------------------------------------------
// Binning pipeline (privatized histograms)
__global__ void zero_bins_kernel() {
    g_cnt[threadIdx.x] = 0;
}

__device__ __forceinline__ int point_bin(int b, float tm1, float tm2) {
    int w1 = ((int)floorf(tm1)) & 511;   // col dim (k1)
    int w2 = ((int)floorf(tm2)) & 511;   // row dim (k2)
    return (b << 6) | ((w2 >> 6) << 3) | (w1 >> 6);
}

__device__ __forceinline__ void load_point(const float* ktraj, int idx,
                                           float& tm1, float& tm2, int& b) {
    b = idx >> 17;
    int m = idx & (M_ - 1);
    const float SC = (float)(512.0 / (2.0 * 3.141592653589793));
    tm1 = ktraj[((size_t)b * 2)     * M_ + m] * SC;
    tm2 = ktraj[((size_t)b * 2 + 1) * M_ + m] * SC;
}

__global__ void __launch_bounds__(HT) count_kernel(const float* __restrict__ ktraj) {
    __shared__ int sh[NBIN];
    int tid = threadIdx.x;
    if (tid < NBIN) sh[tid] = 0;
    __syncthreads();

    int start = blockIdx.x * PPB;
    #pragma unroll 4
    for (int k = tid; k < PPB; k += HT) {
        float tm1, tm2; int b;
        load_point(ktraj, start + k, tm1, tm2, b);
        atomicAdd(&sh[point_bin(b, tm1, tm2)], 1);
    }
    __syncthreads();
    if (tid < NBIN) {
        int v = sh[tid];
        if (v) atomicAdd(&g_cnt[tid], v);
    }
}

__global__ void scan_kernel() {
    __shared__ int sh[NBIN];
    int tid = threadIdx.x;            // 512 threads
    int v = g_cnt[tid];
    sh[tid] = v;
    #pragma unroll
    for (int d = 1; d < NBIN; d <<= 1) {
        __syncthreads();
        int add = (tid >= d) ? sh[tid - d] : 0;
        __syncthreads();
        sh[tid] += add;
    }
    int excl = sh[tid] - v;
    g_off[tid]    = excl;
    g_cursor[tid] = excl;
}

__global__ void __launch_bounds__(HT) scatter_kernel(const float* __restrict__ ktraj,
                                                     const float* __restrict__ dcf) {
    __shared__ int sh[NBIN];          // local histogram, then local write cursor
    int tid = threadIdx.x;
    if (tid < NBIN) sh[tid] = 0;
    __syncthreads();

    int start = blockIdx.x * PPB;

    // Pass A: local histogram
    #pragma unroll 4
    for (int k = tid; k < PPB; k += HT) {
        float tm1, tm2; int b;
        load_point(ktraj, start + k, tm1, tm2, b);
        atomicAdd(&sh[point_bin(b, tm1, tm2)], 1);
    }
    __syncthreads();

    // Phase B: reserve contiguous global range per (block, bin)
    if (tid < NBIN) {
        int v = sh[tid];
        sh[tid] = v ? atomicAdd(&g_cursor[tid], v) : 0;
    }
    __syncthreads();

    // Pass C: place points
    #pragma unroll 4
    for (int k = tid; k < PPB; k += HT) {
        int idx = start + k;
        float tm1, tm2; int b;
        load_point(ktraj, idx, tm1, tm2, b);
        int m = idx & (M_ - 1);
        float d = dcf[(size_t)b * M_ + m];
        int bin = point_bin(b, tm1, tm2);
        int pos = atomicAdd(&sh[bin], 1);
        g_sorted[pos] = make_float4(tm1, tm2, d, __int_as_float(idx));
    }
}

// ---------------------------------------------------------------------------
// Gather: one block per bin. Load (64+5)^2 halo tile into smem, then each
// point reads its 6x6 taps from smem.
__global__ void __launch_bounds__(256) gather_bin_kernel(float* __restrict__ out) {
    __shared__ float2 tile[TROWS * TPITCH];   // 69*71*8 = 39.2 KB

    int bin = blockIdx.x;
    int b   = bin >> 6;
    int t2  = (bin >> 3) & 7;   // row tile (k2)
    int t1  = bin & 7;          // col tile (k1)
    int tid = threadIdx.x;

    int r0 = t2 * TILE - 2;     // may be negative; wrap on use
    int c0 = t1 * TILE - 2;

    const float2* base = g_KGT + (size_t)b * G * G;
    for (int i = tid; i < TROWS * TROWS; i += 256) {
        int lr = i / TROWS;
        int lc = i - lr * TROWS;
        int gr = (r0 + lr) & 511;
        int gc = (c0 + lc) & 511;
        tile[lr * TPITCH + lc] = base[(size_t)gr * G + gc];
    }
    __syncthreads();

    int beg = g_off[bin];
    int end = beg + g_cnt[bin];

    for (int p = beg + tid; p < end; p += 256) {
        float4 pt = g_sorted[p];
        float tm1 = pt.x, tm2 = pt.y, d = pt.z;
        int idx = __float_as_int(pt.w);

        float f1 = floorf(tm1), f2 = floorf(tm2);
        float fr1 = tm1 - f1,   fr2 = tm2 - f2;
        int w1 = ((int)f1) & 511;
        int w2 = ((int)f2) & 511;
        int lc = (w1 & 63) + 2;    // 2..65
        int lr = (w2 & 63) + 2;

        float a1[J_], a2[J_];
        #pragma unroll
        for (int j = 0; j < J_; j++) {
            a1[j] = kb(fr1 - (float)(j - 2));
            a2[j] = kb(fr2 - (float)(j - 2));
        }

        float sre = 0.0f, sim = 0.0f;
        const float2* tp = tile + (lr - 2) * TPITCH + (lc - 2);
        #pragma unroll
        for (int j2 = 0; j2 < J_; j2++) {
            const float2* row = tp + j2 * TPITCH;
            float rre = 0.0f, rim = 0.0f;
            #pragma unroll
            for (int j1 = 0; j1 < J_; j1++) {
                float2 v = row[j1];
                rre = fmaf(a1[j1], v.x, rre);
                rim = fmaf(a1[j1], v.y, rim);
            }
            sre = fmaf(a2[j2], rre, sre);
            sim = fmaf(a2[j2], rim, sim);
        }

        out[idx]           = sre * d;    // (0, b, m)
        out[B_ * M_ + idx] = sim * d;    // (1, b, m)
    }
}

// ---------------------------------------------------------------------------
extern "C" void kernel_launch(void* const* d_in, const int* in_sizes, int n_in,
                              void* d_out, int out_size) {
    const float* image = (const float*)d_in[0];   // (8,256,256)
    const float* ktraj = (const float*)d_in[1];   // (8,2,131072)
    const float* dcf   = (const float*)d_in[2];   // (8,131072)
    float* out = (float*)d_out;                   // (2,8,131072)

    pass1_kernel    <<<B_ * IMN, 128>>>(image);
    pass2_kernel    <<<B_ * G,   128>>>();
    zero_bins_kernel<<<1, NBIN>>>();
    count_kernel    <<<HB, HT>>>(ktraj);
    scan_kernel     <<<1, NBIN>>>();
    scatter_kernel  <<<HB, HT>>>(ktraj, dcf);
    gather_bin_kernel<<<NBIN, 256>>>(out);
}

// round 5
// speedup vs baseline: 3.5738x; 1.0212x over previous
#include <cuda_runtime.h>
#include <math.h>

// ---------------------------------------------------------------------------
// NUFFT type-2:  image(8,256,256) -> kdata(2,8,131072)
//   1) de-apodization (table) folded into pass1
//   2) centered zero-pad 512x512 fft2 == FFT512(zero-pad) * i^{k1} * i^{k2}
//      FFT twiddles precomputed (table) -> no MUFU in the hot loop
//   3) KB 6x6 gather: points binned into 64x64 tiles (fixed-capacity bins,
//      privatized histogram scatter), gather from smem tile
// ---------------------------------------------------------------------------

#define IMN   256
#define G     512
#define B_    8
#define M_    131072            // 2^17
#define NPTS  (B_ * M_)         // 1,048,576
#define J_    6
#define NBIN  512               // 8 batches * 8 * 8 tiles
#define TILE  64
#define TROWS 69                // TILE + 5 halo
#define TPITCH 71               // padded pitch (float2 units)
#define CAP   4096              // per-bin capacity (mean 2048, 5-sigma ~2300)

#define HB    128               // scatter blocks
#define HT    512               // scatter threads/block
#define PPB   (NPTS / HB)       // 8192 points per block

// Scratch (device globals: allocation-free per harness rules)
__device__ float2 g_F2T[B_ * G * IMN];               // pass1 out [b][k2][n1]
__device__ __align__(16) float2 g_KGT[B_ * G * G];   // k-grid    [b][k2][k1]
__device__ float4 g_sorted[NBIN * CAP];              // binned points (32 MB)
__device__ int    g_cnt[NBIN];                       // cursor -> final count
__device__ float2 g_tw[512];                         // twiddle exp(-i pi pos/half) at [half+pos]
__device__ float  g_apod[IMN];

__device__ __forceinline__ float beta_f() {
    return (float)(3.141592653589793 * sqrt(19.45));  // Beatty beta, OS=2, J=6
}

// Abramowitz & Stegun I0 (rel err ~2e-7)
__device__ __forceinline__ float bessi0f(float z) {
    if (z < 3.75f) {
        float t = z * z * (1.0f / 14.0625f);
        return 1.0f + t * (3.5156229f + t * (3.0899424f + t * (1.2067492f +
                     t * (0.2659732f + t * (0.0360768f + t * 0.0045813f)))));
    } else {
        float w = 3.75f / z;
        float p = 0.39894228f + w * (0.01328592f + w * (0.00225319f + w * (-0.00157565f +
                  w * (0.00916281f + w * (-0.02057706f + w * (0.02635537f +
                  w * (-0.01647633f + w * 0.00392377f)))))));
        return p * __expf(z) * rsqrtf(z);
    }
}

__device__ __forceinline__ float kb(float u) {
    float x = u * (1.0f / 3.0f);
    float t = 1.0f - x * x;
    if (t <= 0.0f) return 0.0f;
    return bessi0f(beta_f() * sqrtf(t));
}

__device__ __forceinline__ float2 mul_ik(float2 v, int k) {
    switch (k & 3) {
        case 0:  return v;
        case 1:  return make_float2(-v.y,  v.x);
        case 2:  return make_float2(-v.x, -v.y);
        default: return make_float2( v.y, -v.x);
    }
}

// ---------------------------------------------------------------------------
// Init: twiddle table, apodization table, zero bin counters. One tiny block.
__global__ void init_kernel() {
    int i = threadIdx.x;          // 512 threads
    if (i >= 1) {
        int half = 1 << (31 - __clz(i));
        int pos  = i - half;
        float ang = -3.14159265358979f * (float)pos / (float)half;
        float s, c;
        __sincosf(ang, &s, &c);
        g_tw[i] = make_float2(c, s);
    } else {
        g_tw[0] = make_float2(1.0f, 0.0f);
    }
    if (i < IMN) {
        float x   = (float)i - 128.0f;
        float arg = (float)(3.141592653589793) * 6.0f * x / 512.0f;
        float bb  = beta_f();
        float t   = bb * bb - arg * arg;
        float st  = sqrtf(t);
        g_apod[i] = st / sinhf(st);
    }
    g_cnt[i] = 0;
}

// In-place 512-pt radix-2 DIT FFT (input pre-bit-reversed), 128 threads.
// Twiddles from shared table (no MUFU).
__device__ __forceinline__ void fft512(float2* sh, const float2* tw, int tid) {
    #pragma unroll
    for (int half = 1; half <= 256; half <<= 1) {
        __syncthreads();
        #pragma unroll
        for (int t = tid; t < 256; t += 128) {
            int pos = t & (half - 1);
            int i0  = ((t & ~(half - 1)) << 1) | pos;
            int i1  = i0 + half;
            float2 w = tw[half + pos];
            float2 a = sh[i0];
            float2 b = sh[i1];
            float tr = w.x * b.x - w.y * b.y;
            float ti = w.x * b.y + w.y * b.x;
            sh[i0] = make_float2(a.x + tr, a.y + ti);
            sh[i1] = make_float2(a.x - tr, a.y - ti);
        }
    }
    __syncthreads();
}

// ---------------------------------------------------------------------------
__global__ void pass1_kernel(const float* __restrict__ img) {
    int b  = blockIdx.x >> 8;
    int n1 = blockIdx.x & 255;
    int tid = threadIdx.x;
    __shared__ float2 sh[512];
    __shared__ float2 tw[512];

    #pragma unroll
    for (int i = tid; i < 512; i += 128) tw[i] = g_tw[i];

    float a1 = g_apod[n1];
    const float* row = img + ((size_t)b * IMN + n1) * IMN;
    #pragma unroll
    for (int n = tid; n < 512; n += 128) {
        float v = 0.0f;
        if (n < 256) v = row[n] * g_apod[n] * a1;
        int br = __brev((unsigned)n) >> 23;
        sh[br] = make_float2(v, 0.0f);
    }
    fft512(sh, tw, tid);
    #pragma unroll
    for (int k = tid; k < 512; k += 128) {
        g_F2T[((size_t)b * G + k) * IMN + n1] = mul_ik(sh[k], k);
    }
}

__global__ void pass2_kernel() {
    int b  = blockIdx.x >> 9;
    int k2 = blockIdx.x & 511;
    int tid = threadIdx.x;
    __shared__ float2 sh[512];
    __shared__ float2 tw[512];

    #pragma unroll
    for (int i = tid; i < 512; i += 128) tw[i] = g_tw[i];

    const float2* src = g_F2T + ((size_t)b * G + k2) * IMN;
    #pragma unroll
    for (int n = tid; n < 512; n += 128) {
        float2 v = (n < 256) ? src[n] : make_float2(0.0f, 0.0f);
        int br = __brev((unsigned)n) >> 23;
        sh[br] = v;
    }
    fft512(sh, tw, tid);
    float2* dst = g_KGT + ((size_t)b * G + k2) * G;
    #pragma unroll
    for (int k = tid; k < 512; k += 128) {
        dst[k] = mul_ik(sh[k], k);
    }
}

// ---------------------------------------------------------------------------
// Binning: single scatter kernel with privatized histograms + fixed-cap bins.
__device__ __forceinline__ int point_bin(int b, float tm1, float tm2) {
    int w1 = ((int)floorf(tm1)) & 511;   // col dim (k1)
    int w2 = ((int)floorf(tm2)) & 511;   // row dim (k2)
    return (b << 6) | ((w2 >> 6) << 3) | (w1 >> 6);
}

__device__ __forceinline__ void load_point(const float* ktraj, int idx,
                                           float& tm1, float& tm2, int& b) {
    b = idx >> 17;
    int m = idx & (M_ - 1);
    const float SC = (float)(512.0 / (2.0 * 3.141592653589793));
    tm1 = ktraj[((size_t)b * 2)     * M_ + m] * SC;
    tm2 = ktraj[((size_t)b * 2 + 1) * M_ + m] * SC;
}

__global__ void __launch_bounds__(HT) scatter_kernel(const float* __restrict__ ktraj,
                                                     const float* __restrict__ dcf) {
    __shared__ int sh[NBIN];          // local histogram, then local write cursor
    int tid = threadIdx.x;
    if (tid < NBIN) sh[tid] = 0;
    __syncthreads();

    int start = blockIdx.x * PPB;

    // Pass A: local histogram
    #pragma unroll 4
    for (int k = tid; k < PPB; k += HT) {
        float tm1, tm2; int b;
        load_point(ktraj, start + k, tm1, tm2, b);
        atomicAdd(&sh[point_bin(b, tm1, tm2)], 1);
    }
    __syncthreads();

    // Phase B: reserve contiguous range inside the bin's fixed-cap region
    if (tid < NBIN) {
        int v = sh[tid];
        sh[tid] = v ? atomicAdd(&g_cnt[tid], v) : 0;
    }
    __syncthreads();

    // Pass C: place points
    #pragma unroll 4
    for (int k = tid; k < PPB; k += HT) {
        int idx = start + k;
        float tm1, tm2; int b;
        load_point(ktraj, idx, tm1, tm2, b);
        int m = idx & (M_ - 1);
        float d = dcf[(size_t)b * M_ + m];
        int bin = point_bin(b, tm1, tm2);
        int pos = atomicAdd(&sh[bin], 1);
        if (pos < CAP)
            g_sorted[(size_t)bin * CAP + pos] = make_float4(tm1, tm2, d, __int_as_float(idx));
    }
}

// ---------------------------------------------------------------------------
// Gather: one block per bin. Load (64+5)^2 halo tile into smem, then each
// point reads its 6x6 taps from smem.
__global__ void __launch_bounds__(256) gather_bin_kernel(float* __restrict__ out) {
    __shared__ float2 tile[TROWS * TPITCH];   // 69*71*8 = 39.2 KB

    int bin = blockIdx.x;
    int b   = bin >> 6;
    int t2  = (bin >> 3) & 7;   // row tile (k2)
    int t1  = bin & 7;          // col tile (k1)
    int tid = threadIdx.x;

    int r0 = t2 * TILE - 2;
    int c0 = t1 * TILE - 2;

    const float2* base = g_KGT + (size_t)b * G * G;
    for (int i = tid; i < TROWS * TROWS; i += 256) {
        int lr = i / TROWS;
        int lc = i - lr * TROWS;
        int gr = (r0 + lr) & 511;
        int gc = (c0 + lc) & 511;
        tile[lr * TPITCH + lc] = base[(size_t)gr * G + gc];
    }
    __syncthreads();

    int cnt = g_cnt[bin];
    if (cnt > CAP) cnt = CAP;
    int beg = bin * CAP;

    for (int p = tid; p < cnt; p += 256) {
        float4 pt = g_sorted[(size_t)beg + p];
        float tm1 = pt.x, tm2 = pt.y, d = pt.z;
        int idx = __float_as_int(pt.w);

        float f1 = floorf(tm1), f2 = floorf(tm2);
        float fr1 = tm1 - f1,   fr2 = tm2 - f2;
        int w1 = ((int)f1) & 511;
        int w2 = ((int)f2) & 511;
        int lc = (w1 & 63) + 2;    // 2..65
        int lr = (w2 & 63) + 2;

        float a1[J_], a2[J_];
        #pragma unroll
        for (int j = 0; j < J_; j++) {
            a1[j] = kb(fr1 - (float)(j - 2));
            a2[j] = kb(fr2 - (float)(j - 2));
        }

        float sre = 0.0f, sim = 0.0f;
        const float2* tp = tile + (lr - 2) * TPITCH + (lc - 2);
        #pragma unroll
        for (int j2 = 0; j2 < J_; j2++) {
            const float2* row = tp + j2 * TPITCH;
            float rre = 0.0f, rim = 0.0f;
            #pragma unroll
            for (int j1 = 0; j1 < J_; j1++) {
                float2 v = row[j1];
                rre = fmaf(a1[j1], v.x, rre);
                rim = fmaf(a1[j1], v.y, rim);
            }
            sre = fmaf(a2[j2], rre, sre);
            sim = fmaf(a2[j2], rim, sim);
        }

        out[idx]           = sre * d;    // (0, b, m)
        out[B_ * M_ + idx] = sim * d;    // (1, b, m)
    }
}

// ---------------------------------------------------------------------------
extern "C" void kernel_launch(void* const* d_in, const int* in_sizes, int n_in,
                              void* d_out, int out_size) {
    const float* image = (const float*)d_in[0];   // (8,256,256)
    const float* ktraj = (const float*)d_in[1];   // (8,2,131072)
    const float* dcf   = (const float*)d_in[2];   // (8,131072)
    float* out = (float*)d_out;                   // (2,8,131072)

    init_kernel     <<<1, 512>>>();
    pass1_kernel    <<<B_ * IMN, 128>>>(image);
    pass2_kernel    <<<B_ * G,   128>>>();
    scatter_kernel  <<<HB, HT>>>(ktraj, dcf);
    gather_bin_kernel<<<NBIN, 256>>>(out);
}

// round 6
// speedup vs baseline: 4.5733x; 1.2797x over previous
#include <cuda_runtime.h>
#include <math.h>

// ---------------------------------------------------------------------------
// NUFFT type-2:  image(8,256,256) -> kdata(2,8,131072)
//   1) de-apodization (table) folded into pass1
//   2) centered zero-pad 512x512 fft2 == FFT512(zero-pad) * i^{k1} * i^{k2}
//      FFT512 = 3 register-resident radix-8 rounds, 64 thr/row, XOR-swizzled
//      smem exchanges (conflict-free), only 2 syncs / 2 smem round-trips
//   3) KB 6x6 gather: points binned into 64x64 tiles (fixed-capacity bins,
//      privatized histogram scatter), gather from smem tile
// ---------------------------------------------------------------------------

#define IMN   256
#define G     512
#define B_    8
#define M_    131072            // 2^17
#define NPTS  (B_ * M_)         // 1,048,576
#define J_    6
#define NBIN  512               // 8 batches * 8 * 8 tiles
#define TILE  64
#define TROWS 69                // TILE + 5 halo
#define TPITCH 71               // padded pitch (float2 units)
#define CAP   4096              // per-bin capacity (mean 2048)
#define SPLIT 2                 // gather blocks per bin

#define HB    256               // scatter blocks
#define HT    512               // scatter threads/block
#define PPB   (NPTS / HB)       // 4096 points per block

// Scratch (device globals: allocation-free per harness rules)
__device__ float2 g_F2T[B_ * G * IMN];               // pass1 out [b][k2][n1]
__device__ __align__(16) float2 g_KGT[B_ * G * G];   // k-grid    [b][k2][k1]
__device__ float4 g_sorted[NBIN * CAP];              // binned points (32 MB)
__device__ int    g_cnt[NBIN];                       // cursor -> final count
__device__ float2 g_tw[512];                         // exp(-i pi pos/half) at [half+pos]
__device__ float  g_apod[IMN];

__device__ __forceinline__ float beta_f() {
    return (float)(3.141592653589793 * sqrt(19.45));  // Beatty beta, OS=2, J=6
}

// Abramowitz & Stegun I0 (rel err ~2e-7)
__device__ __forceinline__ float bessi0f(float z) {
    if (z < 3.75f) {
        float t = z * z * (1.0f / 14.0625f);
        return 1.0f + t * (3.5156229f + t * (3.0899424f + t * (1.2067492f +
                     t * (0.2659732f + t * (0.0360768f + t * 0.0045813f)))));
    } else {
        float w = 3.75f / z;
        float p = 0.39894228f + w * (0.01328592f + w * (0.00225319f + w * (-0.00157565f +
                  w * (0.00916281f + w * (-0.02057706f + w * (0.02635537f +
                  w * (-0.01647633f + w * 0.00392377f)))))));
        return p * __expf(z) * rsqrtf(z);
    }
}

__device__ __forceinline__ float kb(float u) {
    float x = u * (1.0f / 3.0f);
    float t = 1.0f - x * x;
    if (t <= 0.0f) return 0.0f;
    return bessi0f(beta_f() * sqrtf(t));
}

__device__ __forceinline__ float2 mul_ik(float2 v, int k) {
    switch (k & 3) {
        case 0:  return v;
        case 1:  return make_float2(-v.y,  v.x);
        case 2:  return make_float2(-v.x, -v.y);
        default: return make_float2( v.y, -v.x);
    }
}

// ---------------------------------------------------------------------------
// complex helpers
__device__ __forceinline__ float2 cmul(float2 a, float2 b) {
    return make_float2(a.x * b.x - a.y * b.y, a.x * b.y + a.y * b.x);
}
__device__ __forceinline__ float2 cadd(float2 a, float2 b) { return make_float2(a.x + b.x, a.y + b.y); }
__device__ __forceinline__ float2 csub(float2 a, float2 b) { return make_float2(a.x - b.x, a.y - b.y); }
__device__ __forceinline__ float2 mulmi(float2 a) { return make_float2(a.y, -a.x); }  // * exp(-i pi/2)

__device__ __forceinline__ void bf(float2& u, float2& v, float2 w) {
    float2 t = cmul(w, v);
    v = csub(u, t);
    u = cadd(u, t);
}

// Radix-8 DIT round on 8 register-resident elements a[j] at network indices
// base + j*h, for stage halves h, 2h, 4h. Generic twiddles wA/wB/wC (pos=base&...).
__device__ __forceinline__ void bfly8(float2* a, float2 wA, float2 wB, float2 wC) {
    const float S = 0.70710678118654752f;
    bf(a[0], a[1], wA); bf(a[2], a[3], wA); bf(a[4], a[5], wA); bf(a[6], a[7], wA);
    float2 wBm = mulmi(wB);
    bf(a[0], a[2], wB);  bf(a[1], a[3], wBm);
    bf(a[4], a[6], wB);  bf(a[5], a[7], wBm);
    float2 wC1 = cmul(wC, make_float2(S, -S));
    float2 wC2 = mulmi(wC);
    float2 wC3 = cmul(wC, make_float2(-S, -S));
    bf(a[0], a[4], wC);  bf(a[1], a[5], wC1);
    bf(a[2], a[6], wC2); bf(a[3], a[7], wC3);
}

__device__ __forceinline__ int swz(int i) { return i ^ (i >> 3); }  // bank swizzle

// ---------------------------------------------------------------------------
// Init: twiddle table, apodization table, zero bin counters.
__global__ void init_kernel() {
    int i = threadIdx.x;          // 512 threads
    if (i >= 1) {
        int half = 1 << (31 - __clz(i));
        int pos  = i - half;
        float ang = -3.14159265358979f * (float)pos / (float)half;
        float s, c;
        __sincosf(ang, &s, &c);
        g_tw[i] = make_float2(c, s);
    } else {
        g_tw[0] = make_float2(1.0f, 0.0f);
    }
    if (i < IMN) {
        float x   = (float)i - 128.0f;
        float arg = (float)(3.141592653589793) * 6.0f * x / 512.0f;
        float bb  = beta_f();
        float t   = bb * bb - arg * arg;
        float st  = sqrtf(t);
        g_apod[i] = st / sinhf(st);
    }
    g_cnt[i] = 0;
}

// rounds 2+3 shared by both passes; a[] holds round-1 output at indices 8t+j
__device__ __forceinline__ void fft_rounds23(float2* a, float2* sh, int t) {
    #pragma unroll
    for (int j = 0; j < 8; j++) sh[swz(8 * t + j)] = a[j];
    __syncthreads();
    int base2 = ((t >> 3) << 6) | (t & 7);
    #pragma unroll
    for (int j = 0; j < 8; j++) a[j] = sh[swz(base2 + 8 * j)];
    {
        int d = t & 7;
        bfly8(a, g_tw[8 + d], g_tw[16 + d], g_tw[32 + d]);
    }
    #pragma unroll
    for (int j = 0; j < 8; j++) sh[swz(base2 + 8 * j)] = a[j];
    __syncthreads();
    #pragma unroll
    for (int j = 0; j < 8; j++) a[j] = sh[swz(t + 64 * j)];
    bfly8(a, g_tw[64 + t], g_tw[128 + t], g_tw[256 + t]);
    // a[j] now = X[t + 64j]
}

// Pass 1: FFT along n2 for each (b, n1); real input row * apod, zero-padded.
// Odd bit-reversed network positions land in the zero-pad -> only 4 loads.
__global__ void __launch_bounds__(64) pass1_kernel(const float* __restrict__ img) {
    int b  = blockIdx.x >> 8;
    int n1 = blockIdx.x & 255;
    int t  = threadIdx.x;       // 0..63
    __shared__ float2 sh[512];

    float a1 = g_apod[n1];
    const float* row = img + ((size_t)b * IMN + n1) * IMN;
    int r6 = __brev((unsigned)t) >> 26;   // rev6(t)

    float2 a[8];
    // network position i = 8t+j holds x[rev3(j)*64 + rev6(t)]; odd j -> pad(0)
    const int rev3e[4] = {0, 2, 1, 3};    // rev3 of j=0,2,4,6
    #pragma unroll
    for (int e = 0; e < 4; e++) {
        int src = (rev3e[e] << 6) | r6;   // < 256
        float v = row[src] * g_apod[src] * a1;
        a[2 * e]     = make_float2(v, 0.0f);
        a[2 * e + 1] = make_float2(0.0f, 0.0f);
    }
    bfly8(a, make_float2(1.f, 0.f), make_float2(1.f, 0.f), make_float2(1.f, 0.f));
    fft_rounds23(a, sh, t);

    #pragma unroll
    for (int j = 0; j < 8; j++) {
        int k = t + 64 * j;
        g_F2T[((size_t)b * G + k) * IMN + n1] = mul_ik(a[j], k);
    }
}

// Pass 2: FFT along n1 for each (b, k2); complex input row, zero-padded.
__global__ void __launch_bounds__(64) pass2_kernel() {
    int b  = blockIdx.x >> 9;
    int k2 = blockIdx.x & 511;
    int t  = threadIdx.x;       // 0..63
    __shared__ float2 sh[512];

    const float2* src = g_F2T + ((size_t)b * G + k2) * IMN;
    int r6 = __brev((unsigned)t) >> 26;

    float2 a[8];
    const int rev3e[4] = {0, 2, 1, 3};
    #pragma unroll
    for (int e = 0; e < 4; e++) {
        int s = (rev3e[e] << 6) | r6;     // < 256
        a[2 * e]     = src[s];
        a[2 * e + 1] = make_float2(0.0f, 0.0f);
    }
    bfly8(a, make_float2(1.f, 0.f), make_float2(1.f, 0.f), make_float2(1.f, 0.f));
    fft_rounds23(a, sh, t);

    float2* dst = g_KGT + ((size_t)b * G + k2) * G;
    #pragma unroll
    for (int j = 0; j < 8; j++) {
        int k = t + 64 * j;
        dst[k] = mul_ik(a[j], k);         // coalesced
    }
}

// ---------------------------------------------------------------------------
// Binning: single scatter kernel with privatized histograms + fixed-cap bins.
__device__ __forceinline__ int point_bin(int b, float tm1, float tm2) {
    int w1 = ((int)floorf(tm1)) & 511;   // col dim (k1)
    int w2 = ((int)floorf(tm2)) & 511;   // row dim (k2)
    return (b << 6) | ((w2 >> 6) << 3) | (w1 >> 6);
}

__device__ __forceinline__ void load_point(const float* ktraj, int idx,
                                           float& tm1, float& tm2, int& b) {
    b = idx >> 17;
    int m = idx & (M_ - 1);
    const float SC = (float)(512.0 / (2.0 * 3.141592653589793));
    tm1 = ktraj[((size_t)b * 2)     * M_ + m] * SC;
    tm2 = ktraj[((size_t)b * 2 + 1) * M_ + m] * SC;
}

__global__ void __launch_bounds__(HT) scatter_kernel(const float* __restrict__ ktraj,
                                                     const float* __restrict__ dcf) {
    __shared__ int sh[NBIN];          // local histogram, then local write cursor
    int tid = threadIdx.x;
    if (tid < NBIN) sh[tid] = 0;
    __syncthreads();

    int start = blockIdx.x * PPB;

    // Pass A: local histogram
    #pragma unroll 4
    for (int k = tid; k < PPB; k += HT) {
        float tm1, tm2; int b;
        load_point(ktraj, start + k, tm1, tm2, b);
        atomicAdd(&sh[point_bin(b, tm1, tm2)], 1);
    }
    __syncthreads();

    // Phase B: reserve contiguous range inside the bin's fixed-cap region
    if (tid < NBIN) {
        int v = sh[tid];
        sh[tid] = v ? atomicAdd(&g_cnt[tid], v) : 0;
    }
    __syncthreads();

    // Pass C: place points
    #pragma unroll 4
    for (int k = tid; k < PPB; k += HT) {
        int idx = start + k;
        float tm1, tm2; int b;
        load_point(ktraj, idx, tm1, tm2, b);
        int m = idx & (M_ - 1);
        float d = dcf[(size_t)b * M_ + m];
        int bin = point_bin(b, tm1, tm2);
        int pos = atomicAdd(&sh[bin], 1);
        if (pos < CAP)
            g_sorted[(size_t)bin * CAP + pos] = make_float4(tm1, tm2, d, __int_as_float(idx));
    }
}

// ---------------------------------------------------------------------------
// Gather: SPLIT blocks per bin. Each loads the (64+5)^2 halo tile into smem,
// then processes its share of the bin's points with 6x6 taps from smem.
__global__ void __launch_bounds__(256) gather_bin_kernel(float* __restrict__ out) {
    __shared__ float2 tile[TROWS * TPITCH];   // 69*71*8 = 39.2 KB

    int bin  = blockIdx.x / SPLIT;
    int part = blockIdx.x - bin * SPLIT;
    int b   = bin >> 6;
    int t2  = (bin >> 3) & 7;   // row tile (k2)
    int t1  = bin & 7;          // col tile (k1)
    int tid = threadIdx.x;

    int r0 = t2 * TILE - 2;
    int c0 = t1 * TILE - 2;

    const float2* base = g_KGT + (size_t)b * G * G;
    for (int i = tid; i < TROWS * TROWS; i += 256) {
        int lr = i / TROWS;
        int lc = i - lr * TROWS;
        int gr = (r0 + lr) & 511;
        int gc = (c0 + lc) & 511;
        tile[lr * TPITCH + lc] = base[(size_t)gr * G + gc];
    }
    __syncthreads();

    int cnt = g_cnt[bin];
    if (cnt > CAP) cnt = CAP;
    int chunk = (cnt + SPLIT - 1) / SPLIT;
    int pbeg  = part * chunk;
    int pend  = pbeg + chunk;
    if (pend > cnt) pend = cnt;
    size_t beg = (size_t)bin * CAP;

    for (int p = pbeg + tid; p < pend; p += 256) {
        float4 pt = g_sorted[beg + p];
        float tm1 = pt.x, tm2 = pt.y, d = pt.z;
        int idx = __float_as_int(pt.w);

        float f1 = floorf(tm1), f2 = floorf(tm2);
        float fr1 = tm1 - f1,   fr2 = tm2 - f2;
        int w1 = ((int)f1) & 511;
        int w2 = ((int)f2) & 511;
        int lc = (w1 & 63) + 2;    // 2..65
        int lr = (w2 & 63) + 2;

        float a1[J_], a2[J_];
        #pragma unroll
        for (int j = 0; j < J_; j++) {
            a1[j] = kb(fr1 - (float)(j - 2));
            a2[j] = kb(fr2 - (float)(j - 2));
        }

        float sre = 0.0f, sim = 0.0f;
        const float2* tp = tile + (lr - 2) * TPITCH + (lc - 2);
        #pragma unroll
        for (int j2 = 0; j2 < J_; j2++) {
            const float2* row = tp + j2 * TPITCH;
            float rre = 0.0f, rim = 0.0f;
            #pragma unroll
            for (int j1 = 0; j1 < J_; j1++) {
                float2 v = row[j1];
                rre = fmaf(a1[j1], v.x, rre);
                rim = fmaf(a1[j1], v.y, rim);
            }
            sre = fmaf(a2[j2], rre, sre);
            sim = fmaf(a2[j2], rim, sim);
        }

        out[idx]           = sre * d;    // (0, b, m)
        out[B_ * M_ + idx] = sim * d;    // (1, b, m)
    }
}

// ---------------------------------------------------------------------------
extern "C" void kernel_launch(void* const* d_in, const int* in_sizes, int n_in,
                              void* d_out, int out_size) {
    const float* image = (const float*)d_in[0];   // (8,256,256)
    const float* ktraj = (const float*)d_in[1];   // (8,2,131072)
    const float* dcf   = (const float*)d_in[2];   // (8,131072)
    float* out = (float*)d_out;                   // (2,8,131072)

    init_kernel      <<<1, 512>>>();
    pass1_kernel     <<<B_ * IMN, 64>>>(image);
    pass2_kernel     <<<B_ * G,   64>>>();
    scatter_kernel   <<<HB, HT>>>(ktraj, dcf);
    gather_bin_kernel<<<NBIN * SPLIT, 256>>>(out);
}